// round 13
// baseline (speedup 1.0000x reference)
#include <cuda_runtime.h>
#include <math.h>

#define N_NODES 100000
#define NFEAT   256
#define HEADS   8
#define HC      64
#define NCLASS  32
#define NEG     0.2f
#define MAX_E   1700000

#define CSR_BLOCKS  148
#define CSR_THREADS 256
#define CSR_SEG     676   // ceil(100000/148)

typedef unsigned long long ull;

// ---------------- scratch ----------------
__device__ float d_h1  [N_NODES * HC];
__device__ float d_h2  [N_NODES * HC];
__device__ float d_als1[N_NODES * HEADS];
__device__ float d_ald1[N_NODES * HEADS];
__device__ float d_m1  [N_NODES * HEADS];
__device__ float d_g   [N_NODES * NCLASS];
__device__ float d_als2[N_NODES];
__device__ float d_ald2[N_NODES];
__device__ float d_m2  [N_NODES];
__device__ int   d_esrc[MAX_E + 32];
__device__ int   d_deg [N_NODES];
__device__ int   d_rowptr[N_NODES + 1];
__device__ int   d_cursor[N_NODES + 1];
__device__ int   d_bsum[160];
__device__ unsigned g_barcnt;   // monotonic grid-barrier counter (never reset)

__device__ __forceinline__ float lrelu(float x){ return x >= 0.f ? x : NEG * x; }

// FMA-only exp, ~2e-6 rel err.
__device__ __forceinline__ float fexp(float x) {
    x = fmaxf(x, -80.f);
    float t = x * 1.442695041f;
    float z = t + 12582912.f;
    int   n = __float_as_int(z) - 0x4B400000;
    float f = t - (z - 12582912.f);
    float p = 1.3333558e-3f;
    p = fmaf(p, f, 9.6181291e-3f);
    p = fmaf(p, f, 5.5504109e-2f);
    p = fmaf(p, f, 2.4022651e-1f);
    p = fmaf(p, f, 6.9314718e-1f);
    p = fmaf(p, f, 1.0f);
    return p * __int_as_float((n << 23) + 0x3F800000);
}

__device__ __forceinline__ ull pack2(float x){
    ull r; asm("mov.b64 %0, {%1, %1};" : "=l"(r) : "f"(x)); return r;
}
__device__ __forceinline__ void fma2(ull& d, ull a, ull b){
    asm("fma.rn.f32x2 %0, %1, %2, %0;" : "+l"(d) : "l"(a), "l"(b));
}
__device__ __forceinline__ void unpack2(ull v, float& lo, float& hi){
    asm("mov.b64 {%0, %1}, %2;" : "=f"(lo), "=f"(hi) : "l"(v));
}

// ---------------- persistent CSR build: zero/hist/scan/scatter in ONE kernel --
__device__ __forceinline__ void grid_sync() {
    __syncthreads();
    if (threadIdx.x == 0) {
        __threadfence();
        unsigned my = atomicAdd(&g_barcnt, 1u) + 1u;
        unsigned target = ((my + CSR_BLOCKS - 1u) / CSR_BLOCKS) * CSR_BLOCKS;
        while (*(volatile unsigned*)&g_barcnt < target) __nanosleep(64);
        __threadfence();
    }
    __syncthreads();
}

__global__ void __launch_bounds__(CSR_THREADS) k_csr(const void* __restrict__ ei, int E) {
    __shared__ int ss[256];
    __shared__ int sm_w[8], sm_base[8];
    __shared__ int sm_carry;

    int t = threadIdx.x;
    int gid = blockIdx.x * CSR_THREADS + t;
    int gstride = CSR_BLOCKS * CSR_THREADS;
    int lane = t & 31, w = t >> 5;

    const int* pi = (const int*)ei;
    bool is64 = (pi[1] == 0 && pi[3] == 0 && pi[5] == 0 && pi[7] == 0);
    const long long* p64 = (const long long*)ei;

    // phase Z: zero degrees
    for (int i = gid; i < N_NODES; i += gstride) d_deg[i] = 0;
    grid_sync();

    // phase C: degree histogram
    for (int e = gid; e < E; e += gstride) {
        int d = is64 ? (int)p64[E + e] : pi[E + e];
        atomicAdd(&d_deg[d], 1);
    }
    grid_sync();

    // phase R: per-block segment sum
    int segb = blockIdx.x * CSR_SEG;
    int sege = min(segb + CSR_SEG, N_NODES);
    {
        int ssum = 0;
        for (int i = segb + t; i < sege; i += CSR_THREADS) ssum += __ldcg(&d_deg[i]);
        #pragma unroll
        for (int o = 16; o > 0; o >>= 1) ssum += __shfl_xor_sync(0xffffffffu, ssum, o);
        if (lane == 0) sm_w[w] = ssum;
        __syncthreads();
        if (t == 0) {
            int tot = 0;
            #pragma unroll
            for (int q = 0; q < 8; q++) tot += sm_w[q];
            d_bsum[blockIdx.x] = tot;
        }
    }
    grid_sync();

    // phase S: exclusive scan of block sums (block 0)
    if (blockIdx.x == 0) {
        int v = (t < CSR_BLOCKS) ? __ldcg(&d_bsum[t]) : 0;
        ss[t] = v;
        __syncthreads();
        for (int o = 1; o < 256; o <<= 1) {
            int tv = (t >= o) ? ss[t - o] : 0;
            __syncthreads();
            ss[t] += tv;
            __syncthreads();
        }
        if (t < CSR_BLOCKS) d_bsum[t] = ss[t] - v;
    }
    grid_sync();

    // phase P: per-segment exclusive scan -> rowptr / cursor
    {
        int running = __ldcg(&d_bsum[blockIdx.x]);
        for (int cs = segb; cs < sege; cs += CSR_THREADS) {
            int i = cs + t;
            int v = (i < sege) ? __ldcg(&d_deg[i]) : 0;
            int incl = v;
            #pragma unroll
            for (int o = 1; o < 32; o <<= 1) {
                int tv = __shfl_up_sync(0xffffffffu, incl, o);
                if (lane >= o) incl += tv;
            }
            if (lane == 31) sm_w[w] = incl;
            __syncthreads();
            if (t == 0) {
                int run2 = 0;
                #pragma unroll
                for (int q = 0; q < 8; q++) { sm_base[q] = run2; run2 += sm_w[q]; }
                sm_carry = run2;
            }
            __syncthreads();
            int excl = running + sm_base[w] + incl - v;
            if (i < sege) { d_rowptr[i] = excl; d_cursor[i] = excl; }
            running += sm_carry;
            __syncthreads();
        }
        if (blockIdx.x == 0 && t == 0) d_rowptr[N_NODES] = E;
    }
    grid_sync();

    // phase T: scatter sources into CSR order
    for (int e = gid; e < E; e += gstride) {
        int s, d;
        if (is64) { s = (int)p64[e]; d = (int)p64[E + e]; }
        else      { s = pi[e];       d = pi[E + e]; }
        int pos = atomicAdd(&d_cursor[d], 1);
        d_esrc[pos] = s;
    }
}

__global__ void knop() {}

// ---------------- K1: h1 = x @ W1, 4x4 tile, K-chunk 16, 3 blocks/SM ---------
__global__ void __launch_bounds__(256, 3) k1_gemm1(
    const float* __restrict__ x, const float* __restrict__ W1,
    const float* __restrict__ a_s, const float* __restrict__ a_d)
{
    __shared__ float xs[2][8 * 128];
    __shared__ float ws[2][8 * 192];

    int t  = threadIdx.x;
    int tx = t & 15;
    int woff = (t >> 4) * 4;
    int base = blockIdx.x * 64;

    bool isx = t < 128;
    int xn = t >> 1, xq = t & 1;
    int gx = min(base + xn, N_NODES - 1);
    const float* xrow = x + (size_t)gx * NFEAT;
    int t2 = t & 127;
    int wk = t2 >> 4, wg = t2 & 15;

    ull acc[4][4];
    #pragma unroll
    for (int m = 0; m < 4; m++)
        #pragma unroll
        for (int j = 0; j < 4; j++) acc[m][j] = 0;

    {
        if (isx) {
            float4 a0 = *(const float4*)(xrow + xq * 8);
            float4 a1 = *(const float4*)(xrow + xq * 8 + 4);
            int kb = xq * 4;
            xs[0][(kb + 0) * 128 + xn * 2 + 0] = a0.x;
            xs[0][(kb + 0) * 128 + xn * 2 + 1] = a0.y;
            xs[0][(kb + 1) * 128 + xn * 2 + 0] = a0.z;
            xs[0][(kb + 1) * 128 + xn * 2 + 1] = a0.w;
            xs[0][(kb + 2) * 128 + xn * 2 + 0] = a1.x;
            xs[0][(kb + 2) * 128 + xn * 2 + 1] = a1.y;
            xs[0][(kb + 3) * 128 + xn * 2 + 0] = a1.z;
            xs[0][(kb + 3) * 128 + xn * 2 + 1] = a1.w;
        } else {
            #pragma unroll
            for (int r = 0; r < 2; r++) {
                int k = wk + 8 * r;
                float4 wv = *(const float4*)(W1 + k * 64 + wg * 4);
                float* wp = &ws[0][(k >> 1) * 192 + wg * 12 + (k & 1)];
                wp[0] = wv.x; wp[2] = wv.y; wp[4] = wv.z; wp[6] = wv.w;
            }
        }
    }
    __syncthreads();

    for (int c = 0; c < 16; c++) {
        int cur = c & 1;
        float4 p0, p1;
        if (c < 15) {
            if (isx) {
                p0 = *(const float4*)(xrow + (c + 1) * 16 + xq * 8);
                p1 = *(const float4*)(xrow + (c + 1) * 16 + xq * 8 + 4);
            } else {
                p0 = *(const float4*)(W1 + ((c + 1) * 16 + wk) * 64 + wg * 4);
                p1 = *(const float4*)(W1 + ((c + 1) * 16 + wk + 8) * 64 + wg * 4);
            }
        }
        #pragma unroll
        for (int kp = 0; kp < 8; kp++) {
            ull xr[4], wr[4];
            {
                ulonglong2 v0 = *(const ulonglong2*)(&xs[cur][kp * 128 + woff * 2]);
                ulonglong2 v1 = *(const ulonglong2*)(&xs[cur][kp * 128 + (woff + 2) * 2]);
                xr[0] = v0.x; xr[1] = v0.y; xr[2] = v1.x; xr[3] = v1.y;
            }
            {
                const float* wb = &ws[cur][kp * 192 + tx * 12];
                ulonglong2 w01 = *(const ulonglong2*)(wb);
                ulonglong2 w23 = *(const ulonglong2*)(wb + 4);
                wr[0] = w01.x; wr[1] = w01.y; wr[2] = w23.x; wr[3] = w23.y;
            }
            #pragma unroll
            for (int m = 0; m < 4; m++)
                #pragma unroll
                for (int j = 0; j < 4; j++)
                    fma2(acc[m][j], xr[m], wr[j]);
        }
        if (c < 15) {
            int nxt = 1 - cur;
            if (isx) {
                int kb = xq * 4;
                xs[nxt][(kb + 0) * 128 + xn * 2 + 0] = p0.x;
                xs[nxt][(kb + 0) * 128 + xn * 2 + 1] = p0.y;
                xs[nxt][(kb + 1) * 128 + xn * 2 + 0] = p0.z;
                xs[nxt][(kb + 1) * 128 + xn * 2 + 1] = p0.w;
                xs[nxt][(kb + 2) * 128 + xn * 2 + 0] = p1.x;
                xs[nxt][(kb + 2) * 128 + xn * 2 + 1] = p1.y;
                xs[nxt][(kb + 3) * 128 + xn * 2 + 0] = p1.z;
                xs[nxt][(kb + 3) * 128 + xn * 2 + 1] = p1.w;
            } else {
                float* wp0 = &ws[nxt][(wk >> 1) * 192 + wg * 12 + (wk & 1)];
                wp0[0] = p0.x; wp0[2] = p0.y; wp0[4] = p0.z; wp0[6] = p0.w;
                int k1 = wk + 8;
                float* wp1 = &ws[nxt][(k1 >> 1) * 192 + wg * 12 + (k1 & 1)];
                wp1[0] = p1.x; wp1[2] = p1.y; wp1[4] = p1.z; wp1[6] = p1.w;
            }
            __syncthreads();
        }
    }

    float4 asv = *(const float4*)(a_s + 4 * tx);
    float4 adv = *(const float4*)(a_d + 4 * tx);

    #pragma unroll
    for (int m = 0; m < 4; m++) {
        int node = base + woff + m;
        bool ok = node < N_NODES;
        float h[4];
        #pragma unroll
        for (int j = 0; j < 4; j++) {
            float lo, hi; unpack2(acc[m][j], lo, hi);
            h[j] = lo + hi;
        }
        if (ok)
            *(float4*)(d_h1 + (size_t)node * 64 + 4 * tx) =
                make_float4(h[0], h[1], h[2], h[3]);
        float ps = h[0] * asv.x + h[1] * asv.y + h[2] * asv.z + h[3] * asv.w;
        float pd = h[0] * adv.x + h[1] * adv.y + h[2] * adv.z + h[3] * adv.w;
        ps += __shfl_xor_sync(0xffffffffu, ps, 1);
        pd += __shfl_xor_sync(0xffffffffu, pd, 1);
        if (ok && (tx & 1) == 0) {
            int gi = node * 8 + (tx >> 1);
            d_als1[gi] = ps;
            d_ald1[gi] = pd;
            d_m1  [gi] = lrelu(ps + pd);
        }
    }
}

// ---------------- kA1: layer-1 pull, 8-lane groups, 4 nodes/warp -------------
// lane L: group g=L>>3 (node), l8=L&7 -> channels 8*l8..8*l8+7 (head = l8).
__global__ void __launch_bounds__(256) kA1(const float* __restrict__ b1) {
    __shared__ float wsh[8][4 * 72];   // per warp: [g][h][9]
    int warp = threadIdx.x >> 5;
    int L = threadIdx.x & 31;
    int g = L >> 3, l8 = L & 7;
    int d = blockIdx.x * 32 + warp * 4 + g;
    float* wsm = &wsh[warp][g * 72];

    float4 aldA = *(const float4*)(d_ald1 + d * 8);
    float4 aldB = *(const float4*)(d_ald1 + d * 8 + 4);
    float4 mA   = *(const float4*)(d_m1   + d * 8);
    float4 mB   = *(const float4*)(d_m1   + d * 8 + 4);

    // self message: 8 channels as 4 f32x2 accumulators
    ulonglong2 s01 = *(const ulonglong2*)(d_h1 + d * 64 + 8 * l8);
    ulonglong2 s23 = *(const ulonglong2*)(d_h1 + d * 64 + 8 * l8 + 4);
    ull acc0 = s01.x, acc1 = s01.y, acc2 = s23.x, acc3 = s23.y;
    float sumw = 0.f;

    int row = d_rowptr[d], end = d_rowptr[d + 1];
    int b = row;
    while (__any_sync(0xffffffffu, b < end)) {
        int e = b + l8;
        bool valid = e < end;
        int sv = -1;
        if (valid) {
            sv = d_esrc[e];
            float4 asA = *(const float4*)(d_als1 + sv * 8);
            float4 asB = *(const float4*)(d_als1 + sv * 8 + 4);
            wsm[0 * 9 + l8] = fexp(lrelu(asA.x + aldA.x) - mA.x);
            wsm[1 * 9 + l8] = fexp(lrelu(asA.y + aldA.y) - mA.y);
            wsm[2 * 9 + l8] = fexp(lrelu(asA.z + aldA.z) - mA.z);
            wsm[3 * 9 + l8] = fexp(lrelu(asA.w + aldA.w) - mA.w);
            wsm[4 * 9 + l8] = fexp(lrelu(asB.x + aldB.x) - mB.x);
            wsm[5 * 9 + l8] = fexp(lrelu(asB.y + aldB.y) - mB.y);
            wsm[6 * 9 + l8] = fexp(lrelu(asB.z + aldB.z) - mB.z);
            wsm[7 * 9 + l8] = fexp(lrelu(asB.w + aldB.w) - mB.w);
        } else {
            #pragma unroll
            for (int h = 0; h < 8; h++) wsm[h * 9 + l8] = 0.f;
        }
        __syncwarp();
        #pragma unroll
        for (int j = 0; j < 8; j++) {
            int s = __shfl_sync(0xffffffffu, sv, (L & 24) + j);
            float wA = wsm[l8 * 9 + j];
            sumw += wA;
            s = s < 0 ? 0 : s;
            const float* hp = d_h1 + (size_t)s * 64 + 8 * l8;
            ulonglong2 h01 = *(const ulonglong2*)(hp);
            ulonglong2 h23 = *(const ulonglong2*)(hp + 4);
            ull wv = pack2(wA);
            fma2(acc0, wv, h01.x);
            fma2(acc1, wv, h01.y);
            fma2(acc2, wv, h23.x);
            fma2(acc3, wv, h23.y);
        }
        __syncwarp();
        b += 8;
    }

    float sinv = 1.f / (sumw + 1.f + 1e-16f);
    float4 bA = *(const float4*)(b1 + 8 * l8);
    float4 bB = *(const float4*)(b1 + 8 * l8 + 4);
    float r0, r1, r2, r3, r4, r5, r6, r7;
    unpack2(acc0, r0, r1); unpack2(acc1, r2, r3);
    unpack2(acc2, r4, r5); unpack2(acc3, r6, r7);
    float v0 = r0 * sinv + bA.x, v1 = r1 * sinv + bA.y;
    float v2 = r2 * sinv + bA.z, v3 = r3 * sinv + bA.w;
    float v4 = r4 * sinv + bB.x, v5 = r5 * sinv + bB.y;
    float v6 = r6 * sinv + bB.z, v7 = r7 * sinv + bB.w;
    v0 = v0 > 0.f ? v0 : fexp(v0) - 1.f;
    v1 = v1 > 0.f ? v1 : fexp(v1) - 1.f;
    v2 = v2 > 0.f ? v2 : fexp(v2) - 1.f;
    v3 = v3 > 0.f ? v3 : fexp(v3) - 1.f;
    v4 = v4 > 0.f ? v4 : fexp(v4) - 1.f;
    v5 = v5 > 0.f ? v5 : fexp(v5) - 1.f;
    v6 = v6 > 0.f ? v6 : fexp(v6) - 1.f;
    v7 = v7 > 0.f ? v7 : fexp(v7) - 1.f;
    *(float4*)(d_h2 + d * 64 + 8 * l8)     = make_float4(v0, v1, v2, v3);
    *(float4*)(d_h2 + d * 64 + 8 * l8 + 4) = make_float4(v4, v5, v6, v7);
}

// ---------------- k5: g = h2 @ W2, layer-2 logits + m2 -----------------------
__global__ void __launch_bounds__(256) k5_prep2(
    const float* __restrict__ W2, const float* __restrict__ a_s2,
    const float* __restrict__ a_d2)
{
    __shared__ float W2s[HC * NCLASS];
    __shared__ float as2s[NCLASS], ad2s[NCLASS];
    int t = threadIdx.x;
    #pragma unroll
    for (int r = 0; r < 8; r++) W2s[r * 256 + t] = W2[r * 256 + t];
    if (t < NCLASS) { as2s[t] = a_s2[t]; ad2s[t] = a_d2[t]; }
    __syncthreads();

    int d = blockIdx.x * 8 + (t >> 5);
    int L = t & 31;
    float h0 = d_h2[d * 64 + L];
    float h1 = d_h2[d * 64 + 32 + L];
    float g = 0.f;
    #pragma unroll
    for (int k = 0; k < 32; k++)
        g += __shfl_sync(0xffffffffu, h0, k) * W2s[k * 32 + L];
    #pragma unroll
    for (int k = 0; k < 32; k++)
        g += __shfl_sync(0xffffffffu, h1, k) * W2s[(32 + k) * 32 + L];
    d_g[d * 32 + L] = g;

    float ps = g * as2s[L];
    float pd = g * ad2s[L];
    #pragma unroll
    for (int o = 16; o > 0; o >>= 1) {
        ps += __shfl_xor_sync(0xffffffffu, ps, o);
        pd += __shfl_xor_sync(0xffffffffu, pd, o);
    }
    if (L == 0) {
        d_als2[d] = ps;
        d_ald2[d] = pd;
        d_m2[d] = lrelu(ps + pd);
    }
}

// ---------------- kA2: layer-2 pull + fused log_softmax ----------------------
__global__ void __launch_bounds__(256) kA2(const float* __restrict__ b2,
                                           float* __restrict__ out) {
    int d = (blockIdx.x * 256 + threadIdx.x) >> 5;
    int L = threadIdx.x & 31;

    float ald = d_ald2[d];
    float m   = d_m2[d];
    float acc = d_g[d * 32 + L];
    float swsum = 0.f;

    int row = d_rowptr[d], end = d_rowptr[d + 1];
    for (int b = row; b < end; b += 32) {
        int cnt = min(32, end - b);
        int sreg = (b + L < end) ? d_esrc[b + L] : -1;
        float w = 0.f;
        if (sreg >= 0) w = fexp(lrelu(d_als2[sreg] + ald) - m);
        swsum += w;
        #pragma unroll 4
        for (int j = 0; j < cnt; j++) {
            int s  = __shfl_sync(0xffffffffu, sreg, j);
            float wj = __shfl_sync(0xffffffffu, w, j);
            acc += wj * d_g[s * 32 + L];
        }
    }
    #pragma unroll
    for (int o = 16; o > 0; o >>= 1)
        swsum += __shfl_xor_sync(0xffffffffu, swsum, o);

    float v = acc * (1.f / (swsum + 1.f + 1e-16f)) + b2[L];
    float mx = v;
    #pragma unroll
    for (int o = 16; o > 0; o >>= 1) mx = fmaxf(mx, __shfl_xor_sync(0xffffffffu, mx, o));
    float se = __expf(v - mx);
    #pragma unroll
    for (int o = 16; o > 0; o >>= 1) se += __shfl_xor_sync(0xffffffffu, se, o);
    out[d * 32 + L] = v - mx - __logf(se);
}

// ---------------- launch ------------------------------------------------------
extern "C" void kernel_launch(void* const* d_in, const int* in_sizes, int n_in,
                              void* d_out, int out_size)
{
    const float* x   = (const float*)d_in[0];
    const void*  ei  = d_in[1];
    const float* W1  = (const float*)d_in[2];
    const float* as1 = (const float*)d_in[3];
    const float* ad1 = (const float*)d_in[4];
    const float* b1  = (const float*)d_in[5];
    const float* W2  = (const float*)d_in[6];
    const float* as2 = (const float*)d_in[7];
    const float* ad2 = (const float*)d_in[8];
    const float* b2  = (const float*)d_in[9];
    float* out = (float*)d_out;

    int E = in_sizes[1] / 2;

    static cudaStream_t s2 = nullptr;
    static cudaEvent_t evF = nullptr, evJ = nullptr;
    if (!s2) {
        cudaStreamCreateWithFlags(&s2, cudaStreamNonBlocking);
        cudaEventCreateWithFlags(&evF, cudaEventDisableTiming);
        cudaEventCreateWithFlags(&evJ, cudaEventDisableTiming);
    }

    // fork: CSR build (one persistent kernel) on s2; GEMM on main stream.
    // evJ is the LAST op on s2 and the main stream waits on it -> fully joined.
    cudaEventRecord(evF, 0);
    cudaStreamWaitEvent(s2, evF, 0);

    k_csr<<<CSR_BLOCKS, CSR_THREADS, 0, s2>>>(ei, E);        // submission 1
    cudaEventRecord(evJ, s2);

    k1_gemm1<<<(N_NODES + 63) / 64, 256>>>(x, W1, as1, ad1);  // submission 2
    knop<<<1, 32>>>();                                        // submission 3 (main)

    cudaStreamWaitEvent(0, evJ, 0);

    kA1     <<<N_NODES / 32, 256>>>(b1);                      // submission 4 (profiled)
    k5_prep2<<<N_NODES / 8, 256>>>(W2, as2, ad2);
    kA2     <<<N_NODES / 8, 256>>>(b2, out);
}

// round 14
// speedup vs baseline: 1.1233x; 1.1233x over previous
#include <cuda_runtime.h>
#include <math.h>

#define N_NODES 100000
#define NFEAT   256
#define HEADS   8
#define HC      64
#define NCLASS  32
#define NEG     0.2f
#define MAX_E   1700000

typedef unsigned long long ull;

// ---------------- scratch ----------------
__device__ float d_h1  [N_NODES * HC];
__device__ float d_h2  [N_NODES * HC];
__device__ float d_als1[N_NODES * HEADS];
__device__ float d_ald1[N_NODES * HEADS];
__device__ float d_m1  [N_NODES * HEADS];
__device__ float d_g   [N_NODES * NCLASS];
__device__ float d_als2[N_NODES];
__device__ float d_ald2[N_NODES];
__device__ float d_m2  [N_NODES];
__device__ int   d_esrc[MAX_E + 32];
__device__ int   d_deg [N_NODES];
__device__ int   d_rowptr[N_NODES + 1];
__device__ int   d_cursor[N_NODES + 1];
__device__ int   d_bsum[128];
__device__ int   d_is64;

__device__ __forceinline__ float lrelu(float x){ return x >= 0.f ? x : NEG * x; }

// FMA-only exp, ~2e-6 rel err.
__device__ __forceinline__ float fexp(float x) {
    x = fmaxf(x, -80.f);
    float t = x * 1.442695041f;
    float z = t + 12582912.f;
    int   n = __float_as_int(z) - 0x4B400000;
    float f = t - (z - 12582912.f);
    float p = 1.3333558e-3f;
    p = fmaf(p, f, 9.6181291e-3f);
    p = fmaf(p, f, 5.5504109e-2f);
    p = fmaf(p, f, 2.4022651e-1f);
    p = fmaf(p, f, 6.9314718e-1f);
    p = fmaf(p, f, 1.0f);
    return p * __int_as_float((n << 23) + 0x3F800000);
}

__device__ __forceinline__ ull pack2(float x){
    ull r; asm("mov.b64 %0, {%1, %1};" : "=l"(r) : "f"(x)); return r;
}
__device__ __forceinline__ void fma2(ull& d, ull a, ull b){
    asm("fma.rn.f32x2 %0, %1, %2, %0;" : "+l"(d) : "l"(a), "l"(b));
}
__device__ __forceinline__ void unpack2(ull v, float& lo, float& hi){
    asm("mov.b64 {%0, %1}, %2;" : "=f"(lo), "=f"(hi) : "l"(v));
}

// ---------------- edge-index prep + CSR build (split chain, round-11) --------
__global__ void k_detect(const void* ei) {
    const int* p = (const int*)ei;
    d_is64 = (p[1] == 0 && p[3] == 0 && p[5] == 0 && p[7] == 0) ? 1 : 0;
}

__global__ void k_zero() {
    int i = blockIdx.x * blockDim.x + threadIdx.x;
    if (i < N_NODES) d_deg[i] = 0;
}

__global__ void k_conv(const void* __restrict__ ei, int E) {
    int e = blockIdx.x * blockDim.x + threadIdx.x;
    if (e >= E) return;
    int d;
    if (d_is64) d = (int)((const long long*)ei)[E + e];
    else        d = ((const int*)ei)[E + e];
    atomicAdd(&d_deg[d], 1);
}

__global__ void __launch_bounds__(1024) kscan1(int nElem) {
    __shared__ int wsum[32], wbase[32];
    int i = blockIdx.x * 1024 + threadIdx.x;
    int v = (i < nElem) ? d_deg[i] : 0;
    int lane = threadIdx.x & 31, w = threadIdx.x >> 5;
    int incl = v;
    #pragma unroll
    for (int o = 1; o < 32; o <<= 1) {
        int t = __shfl_up_sync(0xffffffffu, incl, o);
        if (lane >= o) incl += t;
    }
    if (lane == 31) wsum[w] = incl;
    __syncthreads();
    if (w == 0) {
        int s = wsum[lane], si = s;
        #pragma unroll
        for (int o = 1; o < 32; o <<= 1) {
            int t = __shfl_up_sync(0xffffffffu, si, o);
            if (lane >= o) si += t;
        }
        wbase[lane] = si - s;
    }
    __syncthreads();
    int excl = incl - v + wbase[w];
    if (i < nElem) d_rowptr[i] = excl;
    if (threadIdx.x == 1023) d_bsum[blockIdx.x] = excl + v;
}

__global__ void kscan2(int nb) {
    __shared__ int sm[128];
    int t = threadIdx.x;
    int v = (t < nb) ? d_bsum[t] : 0;
    sm[t] = v;
    __syncthreads();
    for (int o = 1; o < 128; o <<= 1) {
        int tmp = (t >= o) ? sm[t - o] : 0;
        __syncthreads();
        sm[t] += tmp;
        __syncthreads();
    }
    if (t < nb) d_bsum[t] = sm[t] - v;
}

__global__ void kscan3(int E) {
    int i = blockIdx.x * blockDim.x + threadIdx.x;
    if (i < N_NODES) {
        int r = d_rowptr[i] + d_bsum[i >> 10];
        d_rowptr[i] = r;
        d_cursor[i] = r;
    } else if (i == N_NODES) {
        d_rowptr[N_NODES] = E;
    }
}

__global__ void k_scat(const void* __restrict__ ei, int E) {
    int e = blockIdx.x * blockDim.x + threadIdx.x;
    if (e >= E) return;
    int s, d;
    if (d_is64) {
        const long long* p = (const long long*)ei;
        s = (int)p[e]; d = (int)p[E + e];
    } else {
        const int* p = (const int*)ei;
        s = p[e]; d = p[E + e];
    }
    int pos = atomicAdd(&d_cursor[d], 1);
    d_esrc[pos] = s;
}

// ---------------- K1: h1 = x @ W1, 4x4 tile, K-chunk 16, 3 blocks/SM ---------
__global__ void __launch_bounds__(256, 3) k1_gemm1(
    const float* __restrict__ x, const float* __restrict__ W1,
    const float* __restrict__ a_s, const float* __restrict__ a_d)
{
    __shared__ float xs[2][8 * 128];
    __shared__ float ws[2][8 * 192];

    int t  = threadIdx.x;
    int tx = t & 15;
    int woff = (t >> 4) * 4;
    int base = blockIdx.x * 64;

    bool isx = t < 128;
    int xn = t >> 1, xq = t & 1;
    int gx = min(base + xn, N_NODES - 1);
    const float* xrow = x + (size_t)gx * NFEAT;
    int t2 = t & 127;
    int wk = t2 >> 4, wg = t2 & 15;

    ull acc[4][4];
    #pragma unroll
    for (int m = 0; m < 4; m++)
        #pragma unroll
        for (int j = 0; j < 4; j++) acc[m][j] = 0;

    {
        if (isx) {
            float4 a0 = *(const float4*)(xrow + xq * 8);
            float4 a1 = *(const float4*)(xrow + xq * 8 + 4);
            int kb = xq * 4;
            xs[0][(kb + 0) * 128 + xn * 2 + 0] = a0.x;
            xs[0][(kb + 0) * 128 + xn * 2 + 1] = a0.y;
            xs[0][(kb + 1) * 128 + xn * 2 + 0] = a0.z;
            xs[0][(kb + 1) * 128 + xn * 2 + 1] = a0.w;
            xs[0][(kb + 2) * 128 + xn * 2 + 0] = a1.x;
            xs[0][(kb + 2) * 128 + xn * 2 + 1] = a1.y;
            xs[0][(kb + 3) * 128 + xn * 2 + 0] = a1.z;
            xs[0][(kb + 3) * 128 + xn * 2 + 1] = a1.w;
        } else {
            #pragma unroll
            for (int r = 0; r < 2; r++) {
                int k = wk + 8 * r;
                float4 wv = *(const float4*)(W1 + k * 64 + wg * 4);
                float* wp = &ws[0][(k >> 1) * 192 + wg * 12 + (k & 1)];
                wp[0] = wv.x; wp[2] = wv.y; wp[4] = wv.z; wp[6] = wv.w;
            }
        }
    }
    __syncthreads();

    for (int c = 0; c < 16; c++) {
        int cur = c & 1;
        float4 p0, p1;
        if (c < 15) {
            if (isx) {
                p0 = *(const float4*)(xrow + (c + 1) * 16 + xq * 8);
                p1 = *(const float4*)(xrow + (c + 1) * 16 + xq * 8 + 4);
            } else {
                p0 = *(const float4*)(W1 + ((c + 1) * 16 + wk) * 64 + wg * 4);
                p1 = *(const float4*)(W1 + ((c + 1) * 16 + wk + 8) * 64 + wg * 4);
            }
        }
        #pragma unroll
        for (int kp = 0; kp < 8; kp++) {
            ull xr[4], wr[4];
            {
                ulonglong2 v0 = *(const ulonglong2*)(&xs[cur][kp * 128 + woff * 2]);
                ulonglong2 v1 = *(const ulonglong2*)(&xs[cur][kp * 128 + (woff + 2) * 2]);
                xr[0] = v0.x; xr[1] = v0.y; xr[2] = v1.x; xr[3] = v1.y;
            }
            {
                const float* wb = &ws[cur][kp * 192 + tx * 12];
                ulonglong2 w01 = *(const ulonglong2*)(wb);
                ulonglong2 w23 = *(const ulonglong2*)(wb + 4);
                wr[0] = w01.x; wr[1] = w01.y; wr[2] = w23.x; wr[3] = w23.y;
            }
            #pragma unroll
            for (int m = 0; m < 4; m++)
                #pragma unroll
                for (int j = 0; j < 4; j++)
                    fma2(acc[m][j], xr[m], wr[j]);
        }
        if (c < 15) {
            int nxt = 1 - cur;
            if (isx) {
                int kb = xq * 4;
                xs[nxt][(kb + 0) * 128 + xn * 2 + 0] = p0.x;
                xs[nxt][(kb + 0) * 128 + xn * 2 + 1] = p0.y;
                xs[nxt][(kb + 1) * 128 + xn * 2 + 0] = p0.z;
                xs[nxt][(kb + 1) * 128 + xn * 2 + 1] = p0.w;
                xs[nxt][(kb + 2) * 128 + xn * 2 + 0] = p1.x;
                xs[nxt][(kb + 2) * 128 + xn * 2 + 1] = p1.y;
                xs[nxt][(kb + 3) * 128 + xn * 2 + 0] = p1.z;
                xs[nxt][(kb + 3) * 128 + xn * 2 + 1] = p1.w;
            } else {
                float* wp0 = &ws[nxt][(wk >> 1) * 192 + wg * 12 + (wk & 1)];
                wp0[0] = p0.x; wp0[2] = p0.y; wp0[4] = p0.z; wp0[6] = p0.w;
                int k1 = wk + 8;
                float* wp1 = &ws[nxt][(k1 >> 1) * 192 + wg * 12 + (k1 & 1)];
                wp1[0] = p1.x; wp1[2] = p1.y; wp1[4] = p1.z; wp1[6] = p1.w;
            }
            __syncthreads();
        }
    }

    float4 asv = *(const float4*)(a_s + 4 * tx);
    float4 adv = *(const float4*)(a_d + 4 * tx);

    #pragma unroll
    for (int m = 0; m < 4; m++) {
        int node = base + woff + m;
        bool ok = node < N_NODES;
        float h[4];
        #pragma unroll
        for (int j = 0; j < 4; j++) {
            float lo, hi; unpack2(acc[m][j], lo, hi);
            h[j] = lo + hi;
        }
        if (ok)
            *(float4*)(d_h1 + (size_t)node * 64 + 4 * tx) =
                make_float4(h[0], h[1], h[2], h[3]);
        float ps = h[0] * asv.x + h[1] * asv.y + h[2] * asv.z + h[3] * asv.w;
        float pd = h[0] * adv.x + h[1] * adv.y + h[2] * adv.z + h[3] * adv.w;
        ps += __shfl_xor_sync(0xffffffffu, ps, 1);
        pd += __shfl_xor_sync(0xffffffffu, pd, 1);
        if (ok && (tx & 1) == 0) {
            int gi = node * 8 + (tx >> 1);
            d_als1[gi] = ps;
            d_ald1[gi] = pd;
            d_m1  [gi] = lrelu(ps + pd);
        }
    }
}

// ---------------- kA1: layer-1 pull, 8-lane groups, 4 nodes/warp -------------
__global__ void __launch_bounds__(256) kA1(const float* __restrict__ b1) {
    __shared__ float wsh[8][4 * 72];   // per warp: [g][h][9]
    int warp = threadIdx.x >> 5;
    int L = threadIdx.x & 31;
    int g = L >> 3, l8 = L & 7;
    int d = blockIdx.x * 32 + warp * 4 + g;
    float* wsm = &wsh[warp][g * 72];

    float4 aldA = *(const float4*)(d_ald1 + d * 8);
    float4 aldB = *(const float4*)(d_ald1 + d * 8 + 4);
    float4 mA   = *(const float4*)(d_m1   + d * 8);
    float4 mB   = *(const float4*)(d_m1   + d * 8 + 4);

    ulonglong2 s01 = *(const ulonglong2*)(d_h1 + d * 64 + 8 * l8);
    ulonglong2 s23 = *(const ulonglong2*)(d_h1 + d * 64 + 8 * l8 + 4);
    ull acc0 = s01.x, acc1 = s01.y, acc2 = s23.x, acc3 = s23.y;
    float sumw = 0.f;

    int row = d_rowptr[d], end = d_rowptr[d + 1];
    int b = row;
    while (__any_sync(0xffffffffu, b < end)) {
        int e = b + l8;
        bool valid = e < end;
        int sv = -1;
        if (valid) {
            sv = d_esrc[e];
            float4 asA = *(const float4*)(d_als1 + sv * 8);
            float4 asB = *(const float4*)(d_als1 + sv * 8 + 4);
            wsm[0 * 9 + l8] = fexp(lrelu(asA.x + aldA.x) - mA.x);
            wsm[1 * 9 + l8] = fexp(lrelu(asA.y + aldA.y) - mA.y);
            wsm[2 * 9 + l8] = fexp(lrelu(asA.z + aldA.z) - mA.z);
            wsm[3 * 9 + l8] = fexp(lrelu(asA.w + aldA.w) - mA.w);
            wsm[4 * 9 + l8] = fexp(lrelu(asB.x + aldB.x) - mB.x);
            wsm[5 * 9 + l8] = fexp(lrelu(asB.y + aldB.y) - mB.y);
            wsm[6 * 9 + l8] = fexp(lrelu(asB.z + aldB.z) - mB.z);
            wsm[7 * 9 + l8] = fexp(lrelu(asB.w + aldB.w) - mB.w);
        } else {
            #pragma unroll
            for (int h = 0; h < 8; h++) wsm[h * 9 + l8] = 0.f;
        }
        __syncwarp();
        #pragma unroll
        for (int j = 0; j < 8; j++) {
            int s = __shfl_sync(0xffffffffu, sv, (L & 24) + j);
            float wA = wsm[l8 * 9 + j];
            sumw += wA;
            s = s < 0 ? 0 : s;
            const float* hp = d_h1 + (size_t)s * 64 + 8 * l8;
            ulonglong2 h01 = *(const ulonglong2*)(hp);
            ulonglong2 h23 = *(const ulonglong2*)(hp + 4);
            ull wv = pack2(wA);
            fma2(acc0, wv, h01.x);
            fma2(acc1, wv, h01.y);
            fma2(acc2, wv, h23.x);
            fma2(acc3, wv, h23.y);
        }
        __syncwarp();
        b += 8;
    }

    float sinv = 1.f / (sumw + 1.f + 1e-16f);
    float4 bA = *(const float4*)(b1 + 8 * l8);
    float4 bB = *(const float4*)(b1 + 8 * l8 + 4);
    float r0, r1, r2, r3, r4, r5, r6, r7;
    unpack2(acc0, r0, r1); unpack2(acc1, r2, r3);
    unpack2(acc2, r4, r5); unpack2(acc3, r6, r7);
    float v0 = r0 * sinv + bA.x, v1 = r1 * sinv + bA.y;
    float v2 = r2 * sinv + bA.z, v3 = r3 * sinv + bA.w;
    float v4 = r4 * sinv + bB.x, v5 = r5 * sinv + bB.y;
    float v6 = r6 * sinv + bB.z, v7 = r7 * sinv + bB.w;
    v0 = v0 > 0.f ? v0 : fexp(v0) - 1.f;
    v1 = v1 > 0.f ? v1 : fexp(v1) - 1.f;
    v2 = v2 > 0.f ? v2 : fexp(v2) - 1.f;
    v3 = v3 > 0.f ? v3 : fexp(v3) - 1.f;
    v4 = v4 > 0.f ? v4 : fexp(v4) - 1.f;
    v5 = v5 > 0.f ? v5 : fexp(v5) - 1.f;
    v6 = v6 > 0.f ? v6 : fexp(v6) - 1.f;
    v7 = v7 > 0.f ? v7 : fexp(v7) - 1.f;
    *(float4*)(d_h2 + d * 64 + 8 * l8)     = make_float4(v0, v1, v2, v3);
    *(float4*)(d_h2 + d * 64 + 8 * l8 + 4) = make_float4(v4, v5, v6, v7);
}

// ---------------- k5: g = h2 @ W2, layer-2 logits + m2 -----------------------
__global__ void __launch_bounds__(256) k5_prep2(
    const float* __restrict__ W2, const float* __restrict__ a_s2,
    const float* __restrict__ a_d2)
{
    __shared__ float W2s[HC * NCLASS];
    __shared__ float as2s[NCLASS], ad2s[NCLASS];
    int t = threadIdx.x;
    #pragma unroll
    for (int r = 0; r < 8; r++) W2s[r * 256 + t] = W2[r * 256 + t];
    if (t < NCLASS) { as2s[t] = a_s2[t]; ad2s[t] = a_d2[t]; }
    __syncthreads();

    int d = blockIdx.x * 8 + (t >> 5);
    int L = t & 31;
    float h0 = d_h2[d * 64 + L];
    float h1 = d_h2[d * 64 + 32 + L];
    float g = 0.f;
    #pragma unroll
    for (int k = 0; k < 32; k++)
        g += __shfl_sync(0xffffffffu, h0, k) * W2s[k * 32 + L];
    #pragma unroll
    for (int k = 0; k < 32; k++)
        g += __shfl_sync(0xffffffffu, h1, k) * W2s[(32 + k) * 32 + L];
    d_g[d * 32 + L] = g;

    float ps = g * as2s[L];
    float pd = g * ad2s[L];
    #pragma unroll
    for (int o = 16; o > 0; o >>= 1) {
        ps += __shfl_xor_sync(0xffffffffu, ps, o);
        pd += __shfl_xor_sync(0xffffffffu, pd, o);
    }
    if (L == 0) {
        d_als2[d] = ps;
        d_ald2[d] = pd;
        d_m2[d] = lrelu(ps + pd);
    }
}

// ---------------- kA2: layer-2 pull, 16-lane groups, 2 nodes/warp ------------
// lane L: group g=L>>4 (node), l16=L&15 -> channels {2*l16, 2*l16+1}.
__global__ void __launch_bounds__(256) kA2(const float* __restrict__ b2,
                                           float* __restrict__ out) {
    int warp = threadIdx.x >> 5;
    int L = threadIdx.x & 31;
    int l16 = L & 15;
    int d = blockIdx.x * 16 + warp * 2 + (L >> 4);
    int gbase = L & 16;

    float ald = d_ald2[d];
    float m   = d_m2[d];

    ull acc = *(const ull*)(d_g + d * 32 + 2 * l16);   // self message
    float sumw = 0.f;

    int row = d_rowptr[d], end = d_rowptr[d + 1];
    int b = row;
    while (__any_sync(0xffffffffu, b < end)) {
        int e = b + l16;
        bool valid = e < end;
        int sv = -1;
        float w = 0.f;
        if (valid) {
            sv = d_esrc[e];
            w = fexp(lrelu(d_als2[sv] + ald) - m);
        }
        sumw += w;
        #pragma unroll
        for (int j = 0; j < 16; j++) {
            int   s  = __shfl_sync(0xffffffffu, sv, gbase + j);
            float wj = __shfl_sync(0xffffffffu, w,  gbase + j);
            s = s < 0 ? 0 : s;
            ull gv = *(const ull*)(d_g + (size_t)s * 32 + 2 * l16);
            fma2(acc, pack2(wj), gv);
        }
        b += 16;
    }
    // denominator: reduce over the 16-lane group
    #pragma unroll
    for (int o = 8; o > 0; o >>= 1)
        sumw += __shfl_xor_sync(0xffffffffu, sumw, o);

    float sinv = 1.f / (sumw + 1.f + 1e-16f);
    float lo, hi; unpack2(acc, lo, hi);
    float v0 = lo * sinv + b2[2 * l16];
    float v1 = hi * sinv + b2[2 * l16 + 1];

    // log_softmax over the group's 32 channels
    float mx = fmaxf(v0, v1);
    #pragma unroll
    for (int o = 8; o > 0; o >>= 1)
        mx = fmaxf(mx, __shfl_xor_sync(0xffffffffu, mx, o));
    float se = fexp(v0 - mx) + fexp(v1 - mx);
    #pragma unroll
    for (int o = 8; o > 0; o >>= 1)
        se += __shfl_xor_sync(0xffffffffu, se, o);
    float lse = mx + __logf(se);
    *(float2*)(out + d * 32 + 2 * l16) = make_float2(v0 - lse, v1 - lse);
}

// ---------------- launch ------------------------------------------------------
extern "C" void kernel_launch(void* const* d_in, const int* in_sizes, int n_in,
                              void* d_out, int out_size)
{
    const float* x   = (const float*)d_in[0];
    const void*  ei  = d_in[1];
    const float* W1  = (const float*)d_in[2];
    const float* as1 = (const float*)d_in[3];
    const float* ad1 = (const float*)d_in[4];
    const float* b1  = (const float*)d_in[5];
    const float* W2  = (const float*)d_in[6];
    const float* as2 = (const float*)d_in[7];
    const float* ad2 = (const float*)d_in[8];
    const float* b2  = (const float*)d_in[9];
    float* out = (float*)d_out;

    int E  = in_sizes[1] / 2;
    int nb = (N_NODES + 1023) / 1024;

    static cudaStream_t s2 = nullptr;
    static cudaEvent_t evF = nullptr, evJ = nullptr;
    if (!s2) {
        cudaStreamCreateWithFlags(&s2, cudaStreamNonBlocking);
        cudaEventCreateWithFlags(&evF, cudaEventDisableTiming);
        cudaEventCreateWithFlags(&evJ, cudaEventDisableTiming);
    }

    // fork: CSR build chain on s2; GEMM on main stream.
    cudaEventRecord(evF, 0);
    cudaStreamWaitEvent(s2, evF, 0);

    k_detect<<<1, 1, 0, s2>>>(ei);                              // 1
    k_zero  <<<(N_NODES + 255) / 256, 256, 0, s2>>>();          // 2
    k_conv  <<<(E + 255) / 256, 256, 0, s2>>>(ei, E);           // 3

    k1_gemm1<<<(N_NODES + 63) / 64, 256>>>(x, W1, as1, ad1);    // 4 (profiled)

    kscan1  <<<nb, 1024, 0, s2>>>(N_NODES);                     // 5
    kscan2  <<<1, 128, 0, s2>>>(nb);                            // 6
    kscan3  <<<(N_NODES + 256) / 256, 256, 0, s2>>>(E);         // 7
    k_scat  <<<(E + 255) / 256, 256, 0, s2>>>(ei, E);           // 8
    cudaEventRecord(evJ, s2);

    cudaStreamWaitEvent(0, evJ, 0);

    kA1     <<<N_NODES / 32, 256>>>(b1);                        // 9
    k5_prep2<<<N_NODES / 8, 256>>>(W2, as2, ad2);               // 10
    kA2     <<<N_NODES / 16, 256>>>(b2, out);                   // 11
}

// round 15
// speedup vs baseline: 1.2029x; 1.0708x over previous
#include <cuda_runtime.h>
#include <math.h>

#define N_NODES 100000
#define NFEAT   256
#define HEADS   8
#define HC      64
#define NCLASS  32
#define NEG     0.2f
#define MAX_E   1700000

typedef unsigned long long ull;

// ---------------- scratch ----------------
__device__ float d_h1  [N_NODES * HC];
__device__ float d_als1[N_NODES * HEADS];
__device__ float d_ald1[N_NODES * HEADS];
__device__ float d_m1  [N_NODES * HEADS];
__device__ float d_g   [N_NODES * NCLASS];
__device__ float d_als2[N_NODES];
__device__ float d_ald2[N_NODES];
__device__ float d_m2  [N_NODES];
__device__ int   d_esrc[MAX_E + 32];
__device__ int   d_deg [N_NODES];
__device__ int   d_rowptr[N_NODES + 1];
__device__ int   d_cursor[N_NODES + 1];
__device__ int   d_bsum[128];
__device__ int   d_is64;

__device__ __forceinline__ float lrelu(float x){ return x >= 0.f ? x : NEG * x; }

// FMA-only exp, ~2e-6 rel err.
__device__ __forceinline__ float fexp(float x) {
    x = fmaxf(x, -80.f);
    float t = x * 1.442695041f;
    float z = t + 12582912.f;
    int   n = __float_as_int(z) - 0x4B400000;
    float f = t - (z - 12582912.f);
    float p = 1.3333558e-3f;
    p = fmaf(p, f, 9.6181291e-3f);
    p = fmaf(p, f, 5.5504109e-2f);
    p = fmaf(p, f, 2.4022651e-1f);
    p = fmaf(p, f, 6.9314718e-1f);
    p = fmaf(p, f, 1.0f);
    return p * __int_as_float((n << 23) + 0x3F800000);
}

__device__ __forceinline__ ull pack2(float x){
    ull r; asm("mov.b64 %0, {%1, %1};" : "=l"(r) : "f"(x)); return r;
}
__device__ __forceinline__ void fma2(ull& d, ull a, ull b){
    asm("fma.rn.f32x2 %0, %1, %2, %0;" : "+l"(d) : "l"(a), "l"(b));
}
__device__ __forceinline__ void unpack2(ull v, float& lo, float& hi){
    asm("mov.b64 {%0, %1}, %2;" : "=f"(lo), "=f"(hi) : "l"(v));
}

// ---------------- edge-index prep + CSR build (split chain) ------------------
__global__ void k_detect(const void* ei) {
    const int* p = (const int*)ei;
    d_is64 = (p[1] == 0 && p[3] == 0 && p[5] == 0 && p[7] == 0) ? 1 : 0;
}

__global__ void k_zero() {
    int i = blockIdx.x * blockDim.x + threadIdx.x;
    if (i < N_NODES) d_deg[i] = 0;
}

__global__ void k_conv(const void* __restrict__ ei, int E) {
    int e = blockIdx.x * blockDim.x + threadIdx.x;
    if (e >= E) return;
    int d;
    if (d_is64) d = (int)((const long long*)ei)[E + e];
    else        d = ((const int*)ei)[E + e];
    atomicAdd(&d_deg[d], 1);
}

__global__ void __launch_bounds__(1024) kscan1(int nElem) {
    __shared__ int wsum[32], wbase[32];
    int i = blockIdx.x * 1024 + threadIdx.x;
    int v = (i < nElem) ? d_deg[i] : 0;
    int lane = threadIdx.x & 31, w = threadIdx.x >> 5;
    int incl = v;
    #pragma unroll
    for (int o = 1; o < 32; o <<= 1) {
        int t = __shfl_up_sync(0xffffffffu, incl, o);
        if (lane >= o) incl += t;
    }
    if (lane == 31) wsum[w] = incl;
    __syncthreads();
    if (w == 0) {
        int s = wsum[lane], si = s;
        #pragma unroll
        for (int o = 1; o < 32; o <<= 1) {
            int t = __shfl_up_sync(0xffffffffu, si, o);
            if (lane >= o) si += t;
        }
        wbase[lane] = si - s;
    }
    __syncthreads();
    int excl = incl - v + wbase[w];
    if (i < nElem) d_rowptr[i] = excl;
    if (threadIdx.x == 1023) d_bsum[blockIdx.x] = excl + v;
}

__global__ void kscan2(int nb) {
    __shared__ int sm[128];
    int t = threadIdx.x;
    int v = (t < nb) ? d_bsum[t] : 0;
    sm[t] = v;
    __syncthreads();
    for (int o = 1; o < 128; o <<= 1) {
        int tmp = (t >= o) ? sm[t - o] : 0;
        __syncthreads();
        sm[t] += tmp;
        __syncthreads();
    }
    if (t < nb) d_bsum[t] = sm[t] - v;
}

__global__ void kscan3(int E) {
    int i = blockIdx.x * blockDim.x + threadIdx.x;
    if (i < N_NODES) {
        int r = d_rowptr[i] + d_bsum[i >> 10];
        d_rowptr[i] = r;
        d_cursor[i] = r;
    } else if (i == N_NODES) {
        d_rowptr[N_NODES] = E;
    }
}

__global__ void k_scat(const void* __restrict__ ei, int E) {
    int e = blockIdx.x * blockDim.x + threadIdx.x;
    if (e >= E) return;
    int s, d;
    if (d_is64) {
        const long long* p = (const long long*)ei;
        s = (int)p[e]; d = (int)p[E + e];
    } else {
        const int* p = (const int*)ei;
        s = p[e]; d = p[E + e];
    }
    int pos = atomicAdd(&d_cursor[d], 1);
    d_esrc[pos] = s;
}

// ---------------- K1: h1 = x @ W1, 4x4 tile, K-chunk 16, 3 blocks/SM ---------
__global__ void __launch_bounds__(256, 3) k1_gemm1(
    const float* __restrict__ x, const float* __restrict__ W1,
    const float* __restrict__ a_s, const float* __restrict__ a_d)
{
    __shared__ float xs[2][8 * 128];
    __shared__ float ws[2][8 * 192];

    int t  = threadIdx.x;
    int tx = t & 15;
    int woff = (t >> 4) * 4;
    int base = blockIdx.x * 64;

    bool isx = t < 128;
    int xn = t >> 1, xq = t & 1;
    int gx = min(base + xn, N_NODES - 1);
    const float* xrow = x + (size_t)gx * NFEAT;
    int t2 = t & 127;
    int wk = t2 >> 4, wg = t2 & 15;

    ull acc[4][4];
    #pragma unroll
    for (int m = 0; m < 4; m++)
        #pragma unroll
        for (int j = 0; j < 4; j++) acc[m][j] = 0;

    {
        if (isx) {
            float4 a0 = *(const float4*)(xrow + xq * 8);
            float4 a1 = *(const float4*)(xrow + xq * 8 + 4);
            int kb = xq * 4;
            xs[0][(kb + 0) * 128 + xn * 2 + 0] = a0.x;
            xs[0][(kb + 0) * 128 + xn * 2 + 1] = a0.y;
            xs[0][(kb + 1) * 128 + xn * 2 + 0] = a0.z;
            xs[0][(kb + 1) * 128 + xn * 2 + 1] = a0.w;
            xs[0][(kb + 2) * 128 + xn * 2 + 0] = a1.x;
            xs[0][(kb + 2) * 128 + xn * 2 + 1] = a1.y;
            xs[0][(kb + 3) * 128 + xn * 2 + 0] = a1.z;
            xs[0][(kb + 3) * 128 + xn * 2 + 1] = a1.w;
        } else {
            #pragma unroll
            for (int r = 0; r < 2; r++) {
                int k = wk + 8 * r;
                float4 wv = *(const float4*)(W1 + k * 64 + wg * 4);
                float* wp = &ws[0][(k >> 1) * 192 + wg * 12 + (k & 1)];
                wp[0] = wv.x; wp[2] = wv.y; wp[4] = wv.z; wp[6] = wv.w;
            }
        }
    }
    __syncthreads();

    for (int c = 0; c < 16; c++) {
        int cur = c & 1;
        float4 p0, p1;
        if (c < 15) {
            if (isx) {
                p0 = *(const float4*)(xrow + (c + 1) * 16 + xq * 8);
                p1 = *(const float4*)(xrow + (c + 1) * 16 + xq * 8 + 4);
            } else {
                p0 = *(const float4*)(W1 + ((c + 1) * 16 + wk) * 64 + wg * 4);
                p1 = *(const float4*)(W1 + ((c + 1) * 16 + wk + 8) * 64 + wg * 4);
            }
        }
        #pragma unroll
        for (int kp = 0; kp < 8; kp++) {
            ull xr[4], wr[4];
            {
                ulonglong2 v0 = *(const ulonglong2*)(&xs[cur][kp * 128 + woff * 2]);
                ulonglong2 v1 = *(const ulonglong2*)(&xs[cur][kp * 128 + (woff + 2) * 2]);
                xr[0] = v0.x; xr[1] = v0.y; xr[2] = v1.x; xr[3] = v1.y;
            }
            {
                const float* wb = &ws[cur][kp * 192 + tx * 12];
                ulonglong2 w01 = *(const ulonglong2*)(wb);
                ulonglong2 w23 = *(const ulonglong2*)(wb + 4);
                wr[0] = w01.x; wr[1] = w01.y; wr[2] = w23.x; wr[3] = w23.y;
            }
            #pragma unroll
            for (int m = 0; m < 4; m++)
                #pragma unroll
                for (int j = 0; j < 4; j++)
                    fma2(acc[m][j], xr[m], wr[j]);
        }
        if (c < 15) {
            int nxt = 1 - cur;
            if (isx) {
                int kb = xq * 4;
                xs[nxt][(kb + 0) * 128 + xn * 2 + 0] = p0.x;
                xs[nxt][(kb + 0) * 128 + xn * 2 + 1] = p0.y;
                xs[nxt][(kb + 1) * 128 + xn * 2 + 0] = p0.z;
                xs[nxt][(kb + 1) * 128 + xn * 2 + 1] = p0.w;
                xs[nxt][(kb + 2) * 128 + xn * 2 + 0] = p1.x;
                xs[nxt][(kb + 2) * 128 + xn * 2 + 1] = p1.y;
                xs[nxt][(kb + 3) * 128 + xn * 2 + 0] = p1.z;
                xs[nxt][(kb + 3) * 128 + xn * 2 + 1] = p1.w;
            } else {
                float* wp0 = &ws[nxt][(wk >> 1) * 192 + wg * 12 + (wk & 1)];
                wp0[0] = p0.x; wp0[2] = p0.y; wp0[4] = p0.z; wp0[6] = p0.w;
                int k1 = wk + 8;
                float* wp1 = &ws[nxt][(k1 >> 1) * 192 + wg * 12 + (k1 & 1)];
                wp1[0] = p1.x; wp1[2] = p1.y; wp1[4] = p1.z; wp1[6] = p1.w;
            }
            __syncthreads();
        }
    }

    float4 asv = *(const float4*)(a_s + 4 * tx);
    float4 adv = *(const float4*)(a_d + 4 * tx);

    #pragma unroll
    for (int m = 0; m < 4; m++) {
        int node = base + woff + m;
        bool ok = node < N_NODES;
        float h[4];
        #pragma unroll
        for (int j = 0; j < 4; j++) {
            float lo, hi; unpack2(acc[m][j], lo, hi);
            h[j] = lo + hi;
        }
        if (ok)
            *(float4*)(d_h1 + (size_t)node * 64 + 4 * tx) =
                make_float4(h[0], h[1], h[2], h[3]);
        float ps = h[0] * asv.x + h[1] * asv.y + h[2] * asv.z + h[3] * asv.w;
        float pd = h[0] * adv.x + h[1] * adv.y + h[2] * adv.z + h[3] * adv.w;
        ps += __shfl_xor_sync(0xffffffffu, ps, 1);
        pd += __shfl_xor_sync(0xffffffffu, pd, 1);
        if (ok && (tx & 1) == 0) {
            int gi = node * 8 + (tx >> 1);
            d_als1[gi] = ps;
            d_ald1[gi] = pd;
            d_m1  [gi] = lrelu(ps + pd);
        }
    }
}

// ---------------- kA1F: layer-1 pull + FUSED g = h2@W2 + layer-2 logits ------
// 8-lane groups, 4 nodes/warp. lane l8 owns channels 8*l8..+7 (head = l8).
// After edge loop: h2 staged in per-warp smem, g computed in-place (W2 smem).
__global__ void __launch_bounds__(256) kA1F(
    const float* __restrict__ b1, const float* __restrict__ W2,
    const float* __restrict__ a_s2, const float* __restrict__ a_d2)
{
    __shared__ float wsh[8][4 * 72];   // per warp: [g][h][9], reused as h2 stage
    __shared__ float W2s[HC * NCLASS]; // 8 KB, k-major rows of 32
    __shared__ float as2s[NCLASS], ad2s[NCLASS];

    int t = threadIdx.x;
    // cooperative W2 / logit-vector load
    #pragma unroll
    for (int r = 0; r < 2; r++)
        ((float4*)W2s)[r * 256 + t] = ((const float4*)W2)[r * 256 + t];
    if (t < NCLASS) { as2s[t] = a_s2[t]; ad2s[t] = a_d2[t]; }
    __syncthreads();

    int warp = t >> 5;
    int L = t & 31;
    int g = L >> 3, l8 = L & 7;
    int d = blockIdx.x * 32 + warp * 4 + g;
    float* wsm = &wsh[warp][g * 72];

    float4 aldA = *(const float4*)(d_ald1 + d * 8);
    float4 aldB = *(const float4*)(d_ald1 + d * 8 + 4);
    float4 mA   = *(const float4*)(d_m1   + d * 8);
    float4 mB   = *(const float4*)(d_m1   + d * 8 + 4);

    ulonglong2 s01 = *(const ulonglong2*)(d_h1 + d * 64 + 8 * l8);
    ulonglong2 s23 = *(const ulonglong2*)(d_h1 + d * 64 + 8 * l8 + 4);
    ull acc0 = s01.x, acc1 = s01.y, acc2 = s23.x, acc3 = s23.y;
    float sumw = 0.f;

    int row = d_rowptr[d], end = d_rowptr[d + 1];
    int b = row;
    while (__any_sync(0xffffffffu, b < end)) {
        int e = b + l8;
        bool valid = e < end;
        int sv = -1;
        if (valid) {
            sv = d_esrc[e];
            float4 asA = *(const float4*)(d_als1 + sv * 8);
            float4 asB = *(const float4*)(d_als1 + sv * 8 + 4);
            wsm[0 * 9 + l8] = fexp(lrelu(asA.x + aldA.x) - mA.x);
            wsm[1 * 9 + l8] = fexp(lrelu(asA.y + aldA.y) - mA.y);
            wsm[2 * 9 + l8] = fexp(lrelu(asA.z + aldA.z) - mA.z);
            wsm[3 * 9 + l8] = fexp(lrelu(asA.w + aldA.w) - mA.w);
            wsm[4 * 9 + l8] = fexp(lrelu(asB.x + aldB.x) - mB.x);
            wsm[5 * 9 + l8] = fexp(lrelu(asB.y + aldB.y) - mB.y);
            wsm[6 * 9 + l8] = fexp(lrelu(asB.z + aldB.z) - mB.z);
            wsm[7 * 9 + l8] = fexp(lrelu(asB.w + aldB.w) - mB.w);
        } else {
            #pragma unroll
            for (int h = 0; h < 8; h++) wsm[h * 9 + l8] = 0.f;
        }
        __syncwarp();
        #pragma unroll
        for (int j = 0; j < 8; j++) {
            int s = __shfl_sync(0xffffffffu, sv, (L & 24) + j);
            float wA = wsm[l8 * 9 + j];
            sumw += wA;
            s = s < 0 ? 0 : s;
            const float* hp = d_h1 + (size_t)s * 64 + 8 * l8;
            ulonglong2 h01 = *(const ulonglong2*)(hp);
            ulonglong2 h23 = *(const ulonglong2*)(hp + 4);
            ull wv = pack2(wA);
            fma2(acc0, wv, h01.x);
            fma2(acc1, wv, h01.y);
            fma2(acc2, wv, h23.x);
            fma2(acc3, wv, h23.y);
        }
        __syncwarp();
        b += 8;
    }

    // normalize + bias + ELU -> h2 (8 channels per lane)
    float sinv = 1.f / (sumw + 1.f + 1e-16f);
    float4 bA = *(const float4*)(b1 + 8 * l8);
    float4 bB = *(const float4*)(b1 + 8 * l8 + 4);
    float r0, r1, r2, r3, r4, r5, r6, r7;
    unpack2(acc0, r0, r1); unpack2(acc1, r2, r3);
    unpack2(acc2, r4, r5); unpack2(acc3, r6, r7);
    float v0 = r0 * sinv + bA.x, v1 = r1 * sinv + bA.y;
    float v2 = r2 * sinv + bA.z, v3 = r3 * sinv + bA.w;
    float v4 = r4 * sinv + bB.x, v5 = r5 * sinv + bB.y;
    float v6 = r6 * sinv + bB.z, v7 = r7 * sinv + bB.w;
    v0 = v0 > 0.f ? v0 : fexp(v0) - 1.f;
    v1 = v1 > 0.f ? v1 : fexp(v1) - 1.f;
    v2 = v2 > 0.f ? v2 : fexp(v2) - 1.f;
    v3 = v3 > 0.f ? v3 : fexp(v3) - 1.f;
    v4 = v4 > 0.f ? v4 : fexp(v4) - 1.f;
    v5 = v5 > 0.f ? v5 : fexp(v5) - 1.f;
    v6 = v6 > 0.f ? v6 : fexp(v6) - 1.f;
    v7 = v7 > 0.f ? v7 : fexp(v7) - 1.f;

    // stage h2 into per-warp smem (reuse weight scratch)
    __syncwarp();
    *(float4*)(wsm + 8 * l8)     = make_float4(v0, v1, v2, v3);
    *(float4*)(wsm + 8 * l8 + 4) = make_float4(v4, v5, v6, v7);
    __syncwarp();

    // g = h2 @ W2: lane computes cols 4*l8..+3
    int c4 = 4 * l8;
    float g0 = 0.f, g1 = 0.f, g2 = 0.f, g3 = 0.f;
    #pragma unroll 8
    for (int k = 0; k < 64; k++) {
        float hk = wsm[k];
        const float4 wv = *(const float4*)(W2s + k * 32 + c4);
        g0 = fmaf(hk, wv.x, g0);
        g1 = fmaf(hk, wv.y, g1);
        g2 = fmaf(hk, wv.z, g2);
        g3 = fmaf(hk, wv.w, g3);
    }
    *(float4*)(d_g + (size_t)d * 32 + c4) = make_float4(g0, g1, g2, g3);

    // layer-2 logits + m2 (reduce over the 8-lane group)
    float ps = g0 * as2s[c4] + g1 * as2s[c4 + 1] + g2 * as2s[c4 + 2] + g3 * as2s[c4 + 3];
    float pd = g0 * ad2s[c4] + g1 * ad2s[c4 + 1] + g2 * ad2s[c4 + 2] + g3 * ad2s[c4 + 3];
    #pragma unroll
    for (int o = 4; o > 0; o >>= 1) {
        ps += __shfl_xor_sync(0xffffffffu, ps, o);
        pd += __shfl_xor_sync(0xffffffffu, pd, o);
    }
    if (l8 == 0) {
        d_als2[d] = ps;
        d_ald2[d] = pd;
        d_m2[d]   = lrelu(ps + pd);
    }
}

// ---------------- kA2: layer-2 pull, 16-lane groups, 2 nodes/warp ------------
__global__ void __launch_bounds__(256) kA2(const float* __restrict__ b2,
                                           float* __restrict__ out) {
    int warp = threadIdx.x >> 5;
    int L = threadIdx.x & 31;
    int l16 = L & 15;
    int d = blockIdx.x * 16 + warp * 2 + (L >> 4);
    int gbase = L & 16;

    float ald = d_ald2[d];
    float m   = d_m2[d];

    ull acc = *(const ull*)(d_g + d * 32 + 2 * l16);   // self message
    float sumw = 0.f;

    int row = d_rowptr[d], end = d_rowptr[d + 1];
    int b = row;
    while (__any_sync(0xffffffffu, b < end)) {
        int e = b + l16;
        bool valid = e < end;
        int sv = -1;
        float w = 0.f;
        if (valid) {
            sv = d_esrc[e];
            w = fexp(lrelu(d_als2[sv] + ald) - m);
        }
        sumw += w;
        #pragma unroll
        for (int j = 0; j < 16; j++) {
            int   s  = __shfl_sync(0xffffffffu, sv, gbase + j);
            float wj = __shfl_sync(0xffffffffu, w,  gbase + j);
            s = s < 0 ? 0 : s;
            ull gv = *(const ull*)(d_g + (size_t)s * 32 + 2 * l16);
            fma2(acc, pack2(wj), gv);
        }
        b += 16;
    }
    #pragma unroll
    for (int o = 8; o > 0; o >>= 1)
        sumw += __shfl_xor_sync(0xffffffffu, sumw, o);

    float sinv = 1.f / (sumw + 1.f + 1e-16f);
    float lo, hi; unpack2(acc, lo, hi);
    float v0 = lo * sinv + b2[2 * l16];
    float v1 = hi * sinv + b2[2 * l16 + 1];

    float mx = fmaxf(v0, v1);
    #pragma unroll
    for (int o = 8; o > 0; o >>= 1)
        mx = fmaxf(mx, __shfl_xor_sync(0xffffffffu, mx, o));
    float se = fexp(v0 - mx) + fexp(v1 - mx);
    #pragma unroll
    for (int o = 8; o > 0; o >>= 1)
        se += __shfl_xor_sync(0xffffffffu, se, o);
    float lse = mx + __logf(se);
    *(float2*)(out + d * 32 + 2 * l16) = make_float2(v0 - lse, v1 - lse);
}

// ---------------- launch ------------------------------------------------------
extern "C" void kernel_launch(void* const* d_in, const int* in_sizes, int n_in,
                              void* d_out, int out_size)
{
    const float* x   = (const float*)d_in[0];
    const void*  ei  = d_in[1];
    const float* W1  = (const float*)d_in[2];
    const float* as1 = (const float*)d_in[3];
    const float* ad1 = (const float*)d_in[4];
    const float* b1  = (const float*)d_in[5];
    const float* W2  = (const float*)d_in[6];
    const float* as2 = (const float*)d_in[7];
    const float* ad2 = (const float*)d_in[8];
    const float* b2  = (const float*)d_in[9];
    float* out = (float*)d_out;

    int E  = in_sizes[1] / 2;
    int nb = (N_NODES + 1023) / 1024;

    static cudaStream_t s2 = nullptr;
    static cudaEvent_t evF = nullptr, evJ = nullptr;
    if (!s2) {
        cudaStreamCreateWithFlags(&s2, cudaStreamNonBlocking);
        cudaEventCreateWithFlags(&evF, cudaEventDisableTiming);
        cudaEventCreateWithFlags(&evJ, cudaEventDisableTiming);
    }

    // fork: CSR build chain on s2; GEMM on main stream.
    cudaEventRecord(evF, 0);
    cudaStreamWaitEvent(s2, evF, 0);

    k_detect<<<1, 1, 0, s2>>>(ei);                              // 1
    k_zero  <<<(N_NODES + 255) / 256, 256, 0, s2>>>();          // 2
    k_conv  <<<(E + 255) / 256, 256, 0, s2>>>(ei, E);           // 3

    k1_gemm1<<<(N_NODES + 63) / 64, 256>>>(x, W1, as1, ad1);    // 4 (profiled)

    kscan1  <<<nb, 1024, 0, s2>>>(N_NODES);                     // 5
    kscan2  <<<1, 128, 0, s2>>>(nb);                            // 6
    kscan3  <<<(N_NODES + 256) / 256, 256, 0, s2>>>(E);         // 7
    k_scat  <<<(E + 255) / 256, 256, 0, s2>>>(ei, E);           // 8
    cudaEventRecord(evJ, s2);

    cudaStreamWaitEvent(0, evJ, 0);

    kA1F    <<<N_NODES / 32, 256>>>(b1, W2, as2, ad2);          // 9 (fused)
    kA2     <<<N_NODES / 16, 256>>>(b2, out);                   // 10
}

// round 17
// speedup vs baseline: 1.3709x; 1.1397x over previous
#include <cuda_runtime.h>
#include <math.h>

#define N_NODES 100000
#define NFEAT   256
#define HEADS   8
#define HC      64
#define NCLASS  32
#define NEG     0.2f
#define MAX_E   1700000

typedef unsigned long long ull;

// ---------------- scratch ----------------
__device__ float d_h1  [N_NODES * HC];
__device__ float d_als1[N_NODES * HEADS];
__device__ float d_ald1[N_NODES * HEADS];
__device__ float d_m1  [N_NODES * HEADS];
__device__ float d_g   [N_NODES * NCLASS];
__device__ float d_als2[N_NODES];
__device__ float d_ald2[N_NODES];
__device__ float d_m2  [N_NODES];
__device__ int   d_esrc[MAX_E + 32];
__device__ int   d_deg [N_NODES];
__device__ int   d_rowptr[N_NODES + 1];
__device__ int   d_cursor[N_NODES + 1];
__device__ int   d_bsum[128];
__device__ int   d_is64;

__device__ __forceinline__ float lrelu(float x){ return x >= 0.f ? x : NEG * x; }

// FMA-only exp, ~2e-6 rel err.
__device__ __forceinline__ float fexp(float x) {
    x = fmaxf(x, -80.f);
    float t = x * 1.442695041f;
    float z = t + 12582912.f;
    int   n = __float_as_int(z) - 0x4B400000;
    float f = t - (z - 12582912.f);
    float p = 1.3333558e-3f;
    p = fmaf(p, f, 9.6181291e-3f);
    p = fmaf(p, f, 5.5504109e-2f);
    p = fmaf(p, f, 2.4022651e-1f);
    p = fmaf(p, f, 6.9314718e-1f);
    p = fmaf(p, f, 1.0f);
    return p * __int_as_float((n << 23) + 0x3F800000);
}

__device__ __forceinline__ ull pack2(float x){
    ull r; asm("mov.b64 %0, {%1, %1};" : "=l"(r) : "f"(x)); return r;
}
__device__ __forceinline__ void fma2(ull& d, ull a, ull b){
    asm("fma.rn.f32x2 %0, %1, %2, %0;" : "+l"(d) : "l"(a), "l"(b));
}
__device__ __forceinline__ void unpack2(ull v, float& lo, float& hi){
    asm("mov.b64 {%0, %1}, %2;" : "=f"(lo), "=f"(hi) : "l"(v));
}

// ---------------- edge-index prep + CSR build (split chain) ------------------
__global__ void k_detect(const void* ei) {
    const int* p = (const int*)ei;
    d_is64 = (p[1] == 0 && p[3] == 0 && p[5] == 0 && p[7] == 0) ? 1 : 0;
}

__global__ void k_zero() {
    int i = blockIdx.x * blockDim.x + threadIdx.x;
    if (i < N_NODES) d_deg[i] = 0;
}

__global__ void k_conv(const void* __restrict__ ei, int E) {
    int e = blockIdx.x * blockDim.x + threadIdx.x;
    if (e >= E) return;
    int d;
    if (d_is64) d = (int)((const long long*)ei)[E + e];
    else        d = ((const int*)ei)[E + e];
    atomicAdd(&d_deg[d], 1);
}

__global__ void __launch_bounds__(1024) kscan1(int nElem) {
    __shared__ int wsum[32], wbase[32];
    int i = blockIdx.x * 1024 + threadIdx.x;
    int v = (i < nElem) ? d_deg[i] : 0;
    int lane = threadIdx.x & 31, w = threadIdx.x >> 5;
    int incl = v;
    #pragma unroll
    for (int o = 1; o < 32; o <<= 1) {
        int t = __shfl_up_sync(0xffffffffu, incl, o);
        if (lane >= o) incl += t;
    }
    if (lane == 31) wsum[w] = incl;
    __syncthreads();
    if (w == 0) {
        int s = wsum[lane], si = s;
        #pragma unroll
        for (int o = 1; o < 32; o <<= 1) {
            int t = __shfl_up_sync(0xffffffffu, si, o);
            if (lane >= o) si += t;
        }
        wbase[lane] = si - s;
    }
    __syncthreads();
    int excl = incl - v + wbase[w];
    if (i < nElem) d_rowptr[i] = excl;
    if (threadIdx.x == 1023) d_bsum[blockIdx.x] = excl + v;
}

__global__ void kscan2(int nb) {
    __shared__ int sm[128];
    int t = threadIdx.x;
    int v = (t < nb) ? d_bsum[t] : 0;
    sm[t] = v;
    __syncthreads();
    for (int o = 1; o < 128; o <<= 1) {
        int tmp = (t >= o) ? sm[t - o] : 0;
        __syncthreads();
        sm[t] += tmp;
        __syncthreads();
    }
    if (t < nb) d_bsum[t] = sm[t] - v;
}

__global__ void kscan3(int E) {
    int i = blockIdx.x * blockDim.x + threadIdx.x;
    if (i < N_NODES) {
        int r = d_rowptr[i] + d_bsum[i >> 10];
        d_rowptr[i] = r;
        d_cursor[i] = r;
    } else if (i == N_NODES) {
        d_rowptr[N_NODES] = E;
    }
}

__global__ void k_scat(const void* __restrict__ ei, int E) {
    int e = blockIdx.x * blockDim.x + threadIdx.x;
    if (e >= E) return;
    int s, d;
    if (d_is64) {
        const long long* p = (const long long*)ei;
        s = (int)p[e]; d = (int)p[E + e];
    } else {
        const int* p = (const int*)ei;
        s = p[e]; d = p[E + e];
    }
    int pos = atomicAdd(&d_cursor[d], 1);
    d_esrc[pos] = s;
}

// ---------------- K1: h1 = x @ W1, 4x4 tile, K-chunk 8, 4 blocks/SM ----------
__global__ void __launch_bounds__(256, 4) k1_gemm1(
    const float* __restrict__ x, const float* __restrict__ W1,
    const float* __restrict__ a_s, const float* __restrict__ a_d)
{
    __shared__ float xs[2][4 * 128];     // 4 KB
    __shared__ float ws[2][4 * 192];     // 6 KB

    int t  = threadIdx.x;
    int tx = t & 15;
    int woff = (t >> 4) * 4;
    int base = blockIdx.x * 64;

    bool isx = t < 128;
    int xn = t >> 1, xq = t & 1;
    int gx = min(base + xn, N_NODES - 1);
    const float* xrow = x + (size_t)gx * NFEAT;
    int t2 = t & 127;
    int wk = t2 >> 4, wkp = wk >> 1, wpar = wk & 1, wg = t2 & 15;

    ull acc[4][4];
    #pragma unroll
    for (int m = 0; m < 4; m++)
        #pragma unroll
        for (int j = 0; j < 4; j++) acc[m][j] = 0;

    {
        if (isx) {
            float4 a = *(const float4*)(xrow + xq * 4);
            xs[0][(2 * xq)     * 128 + xn * 2 + 0] = a.x;
            xs[0][(2 * xq)     * 128 + xn * 2 + 1] = a.y;
            xs[0][(2 * xq + 1) * 128 + xn * 2 + 0] = a.z;
            xs[0][(2 * xq + 1) * 128 + xn * 2 + 1] = a.w;
        } else {
            float4 wv = *(const float4*)(W1 + wk * 64 + wg * 4);
            float* wp = &ws[0][wkp * 192 + wg * 12 + wpar];
            wp[0] = wv.x; wp[2] = wv.y; wp[4] = wv.z; wp[6] = wv.w;
        }
    }
    __syncthreads();

    for (int c = 0; c < 32; c++) {
        int cur = c & 1;
        float4 pf;
        if (c < 31) {
            if (isx) pf = *(const float4*)(xrow + (c + 1) * 8 + xq * 4);
            else     pf = *(const float4*)(W1 + ((c + 1) * 8 + wk) * 64 + wg * 4);
        }
        #pragma unroll
        for (int kp = 0; kp < 4; kp++) {
            ull xr[4], wr[4];
            {
                ulonglong2 v0 = *(const ulonglong2*)(&xs[cur][kp * 128 + woff * 2]);
                ulonglong2 v1 = *(const ulonglong2*)(&xs[cur][kp * 128 + (woff + 2) * 2]);
                xr[0] = v0.x; xr[1] = v0.y; xr[2] = v1.x; xr[3] = v1.y;
            }
            {
                const float* wb = &ws[cur][kp * 192 + tx * 12];
                ulonglong2 w01 = *(const ulonglong2*)(wb);
                ulonglong2 w23 = *(const ulonglong2*)(wb + 4);
                wr[0] = w01.x; wr[1] = w01.y; wr[2] = w23.x; wr[3] = w23.y;
            }
            #pragma unroll
            for (int m = 0; m < 4; m++)
                #pragma unroll
                for (int j = 0; j < 4; j++)
                    fma2(acc[m][j], xr[m], wr[j]);
        }
        if (c < 31) {
            int nxt = 1 - cur;
            if (isx) {
                xs[nxt][(2 * xq)     * 128 + xn * 2 + 0] = pf.x;
                xs[nxt][(2 * xq)     * 128 + xn * 2 + 1] = pf.y;
                xs[nxt][(2 * xq + 1) * 128 + xn * 2 + 0] = pf.z;
                xs[nxt][(2 * xq + 1) * 128 + xn * 2 + 1] = pf.w;
            } else {
                float* wp = &ws[nxt][wkp * 192 + wg * 12 + wpar];
                wp[0] = pf.x; wp[2] = pf.y; wp[4] = pf.z; wp[6] = pf.w;
            }
            __syncthreads();
        }
    }

    float4 asv = *(const float4*)(a_s + 4 * tx);
    float4 adv = *(const float4*)(a_d + 4 * tx);

    #pragma unroll
    for (int m = 0; m < 4; m++) {
        int node = base + woff + m;
        bool ok = node < N_NODES;
        float h[4];
        #pragma unroll
        for (int j = 0; j < 4; j++) {
            float lo, hi; unpack2(acc[m][j], lo, hi);
            h[j] = lo + hi;
        }
        if (ok)
            *(float4*)(d_h1 + (size_t)node * 64 + 4 * tx) =
                make_float4(h[0], h[1], h[2], h[3]);
        float ps = h[0] * asv.x + h[1] * asv.y + h[2] * asv.z + h[3] * asv.w;
        float pd = h[0] * adv.x + h[1] * adv.y + h[2] * adv.z + h[3] * adv.w;
        ps += __shfl_xor_sync(0xffffffffu, ps, 1);
        pd += __shfl_xor_sync(0xffffffffu, pd, 1);
        if (ok && (tx & 1) == 0) {
            int gi = node * 8 + (tx >> 1);
            d_als1[gi] = ps;
            d_ald1[gi] = pd;
            d_m1  [gi] = lrelu(ps + pd);
        }
    }
}

// ---------------- kA1F: layer-1 pull + FUSED g = h2@W2 + layer-2 logits ------
// Shuffles are ALWAYS convergent; only the gather/FMA sit under j<cnt.
__global__ void __launch_bounds__(256) kA1F(
    const float* __restrict__ b1, const float* __restrict__ W2,
    const float* __restrict__ a_s2, const float* __restrict__ a_d2)
{
    __shared__ float wsh[8][4 * 72];
    __shared__ float W2s[HC * NCLASS];
    __shared__ float as2s[NCLASS], ad2s[NCLASS];

    int t = threadIdx.x;
    #pragma unroll
    for (int r = 0; r < 2; r++)
        ((float4*)W2s)[r * 256 + t] = ((const float4*)W2)[r * 256 + t];
    if (t < NCLASS) { as2s[t] = a_s2[t]; ad2s[t] = a_d2[t]; }
    __syncthreads();

    int warp = t >> 5;
    int L = t & 31;
    int g = L >> 3, l8 = L & 7;
    int d = blockIdx.x * 32 + warp * 4 + g;
    float* wsm = &wsh[warp][g * 72];

    float4 aldA = *(const float4*)(d_ald1 + d * 8);
    float4 aldB = *(const float4*)(d_ald1 + d * 8 + 4);
    float4 mA   = *(const float4*)(d_m1   + d * 8);
    float4 mB   = *(const float4*)(d_m1   + d * 8 + 4);

    ulonglong2 s01 = *(const ulonglong2*)(d_h1 + d * 64 + 8 * l8);
    ulonglong2 s23 = *(const ulonglong2*)(d_h1 + d * 64 + 8 * l8 + 4);
    ull acc0 = s01.x, acc1 = s01.y, acc2 = s23.x, acc3 = s23.y;
    float sumw = 0.f;

    int row = d_rowptr[d], end = d_rowptr[d + 1];
    int b = row;
    while (__any_sync(0xffffffffu, b < end)) {
        int e = b + l8;
        bool valid = e < end;
        int sv = -1;
        if (valid) {
            sv = d_esrc[e];
            float4 asA = *(const float4*)(d_als1 + sv * 8);
            float4 asB = *(const float4*)(d_als1 + sv * 8 + 4);
            wsm[0 * 9 + l8] = fexp(lrelu(asA.x + aldA.x) - mA.x);
            wsm[1 * 9 + l8] = fexp(lrelu(asA.y + aldA.y) - mA.y);
            wsm[2 * 9 + l8] = fexp(lrelu(asA.z + aldA.z) - mA.z);
            wsm[3 * 9 + l8] = fexp(lrelu(asA.w + aldA.w) - mA.w);
            wsm[4 * 9 + l8] = fexp(lrelu(asB.x + aldB.x) - mB.x);
            wsm[5 * 9 + l8] = fexp(lrelu(asB.y + aldB.y) - mB.y);
            wsm[6 * 9 + l8] = fexp(lrelu(asB.z + aldB.z) - mB.z);
            wsm[7 * 9 + l8] = fexp(lrelu(asB.w + aldB.w) - mB.w);
        }
        __syncwarp();
        int cnt = min(8, end - b);          // per-group; may differ across groups
        #pragma unroll
        for (int j = 0; j < 8; j++) {
            int s = __shfl_sync(0xffffffffu, sv, (L & 24) + j);  // convergent
            if (j < cnt) {
                float wA = wsm[l8 * 9 + j];
                sumw += wA;
                const float* hp = d_h1 + (size_t)s * 64 + 8 * l8;
                ulonglong2 h01 = *(const ulonglong2*)(hp);
                ulonglong2 h23 = *(const ulonglong2*)(hp + 4);
                ull wv = pack2(wA);
                fma2(acc0, wv, h01.x);
                fma2(acc1, wv, h01.y);
                fma2(acc2, wv, h23.x);
                fma2(acc3, wv, h23.y);
            }
        }
        __syncwarp();
        b += 8;
    }

    float sinv = 1.f / (sumw + 1.f + 1e-16f);
    float4 bA = *(const float4*)(b1 + 8 * l8);
    float4 bB = *(const float4*)(b1 + 8 * l8 + 4);
    float r0, r1, r2, r3, r4, r5, r6, r7;
    unpack2(acc0, r0, r1); unpack2(acc1, r2, r3);
    unpack2(acc2, r4, r5); unpack2(acc3, r6, r7);
    float v0 = r0 * sinv + bA.x, v1 = r1 * sinv + bA.y;
    float v2 = r2 * sinv + bA.z, v3 = r3 * sinv + bA.w;
    float v4 = r4 * sinv + bB.x, v5 = r5 * sinv + bB.y;
    float v6 = r6 * sinv + bB.z, v7 = r7 * sinv + bB.w;
    v0 = v0 > 0.f ? v0 : fexp(v0) - 1.f;
    v1 = v1 > 0.f ? v1 : fexp(v1) - 1.f;
    v2 = v2 > 0.f ? v2 : fexp(v2) - 1.f;
    v3 = v3 > 0.f ? v3 : fexp(v3) - 1.f;
    v4 = v4 > 0.f ? v4 : fexp(v4) - 1.f;
    v5 = v5 > 0.f ? v5 : fexp(v5) - 1.f;
    v6 = v6 > 0.f ? v6 : fexp(v6) - 1.f;
    v7 = v7 > 0.f ? v7 : fexp(v7) - 1.f;

    __syncwarp();
    *(float4*)(wsm + 8 * l8)     = make_float4(v0, v1, v2, v3);
    *(float4*)(wsm + 8 * l8 + 4) = make_float4(v4, v5, v6, v7);
    __syncwarp();

    int c4 = 4 * l8;
    float g0 = 0.f, g1 = 0.f, g2 = 0.f, g3 = 0.f;
    #pragma unroll 8
    for (int k = 0; k < 64; k++) {
        float hk = wsm[k];
        const float4 wv = *(const float4*)(W2s + k * 32 + c4);
        g0 = fmaf(hk, wv.x, g0);
        g1 = fmaf(hk, wv.y, g1);
        g2 = fmaf(hk, wv.z, g2);
        g3 = fmaf(hk, wv.w, g3);
    }
    *(float4*)(d_g + (size_t)d * 32 + c4) = make_float4(g0, g1, g2, g3);

    float ps = g0 * as2s[c4] + g1 * as2s[c4 + 1] + g2 * as2s[c4 + 2] + g3 * as2s[c4 + 3];
    float pd = g0 * ad2s[c4] + g1 * ad2s[c4 + 1] + g2 * ad2s[c4 + 2] + g3 * ad2s[c4 + 3];
    #pragma unroll
    for (int o = 4; o > 0; o >>= 1) {
        ps += __shfl_xor_sync(0xffffffffu, ps, o);
        pd += __shfl_xor_sync(0xffffffffu, pd, o);
    }
    if (l8 == 0) {
        d_als2[d] = ps;
        d_ald2[d] = pd;
        d_m2[d]   = lrelu(ps + pd);
    }
}

// ---------------- kA2: layer-2 pull, 16-lane groups, 2 nodes/warp ------------
__global__ void __launch_bounds__(256) kA2(const float* __restrict__ b2,
                                           float* __restrict__ out) {
    int warp = threadIdx.x >> 5;
    int L = threadIdx.x & 31;
    int l16 = L & 15;
    int d = blockIdx.x * 16 + warp * 2 + (L >> 4);
    int gbase = L & 16;

    float ald = d_ald2[d];
    float m   = d_m2[d];

    ull acc = *(const ull*)(d_g + d * 32 + 2 * l16);
    float sumw = 0.f;

    int row = d_rowptr[d], end = d_rowptr[d + 1];
    int b = row;
    while (__any_sync(0xffffffffu, b < end)) {
        int e = b + l16;
        bool valid = e < end;
        int sv = -1;
        float w = 0.f;
        if (valid) {
            sv = d_esrc[e];
            w = fexp(lrelu(d_als2[sv] + ald) - m);
        }
        sumw += w;
        int cnt = min(16, end - b);
        #pragma unroll
        for (int j = 0; j < 16; j++) {
            int   s  = __shfl_sync(0xffffffffu, sv, gbase + j);  // convergent
            float wj = __shfl_sync(0xffffffffu, w,  gbase + j);  // convergent
            if (j < cnt) {
                ull gv = *(const ull*)(d_g + (size_t)s * 32 + 2 * l16);
                fma2(acc, pack2(wj), gv);
            }
        }
        b += 16;
    }
    #pragma unroll
    for (int o = 8; o > 0; o >>= 1)
        sumw += __shfl_xor_sync(0xffffffffu, sumw, o);

    float sinv = 1.f / (sumw + 1.f + 1e-16f);
    float lo, hi; unpack2(acc, lo, hi);
    float v0 = lo * sinv + b2[2 * l16];
    float v1 = hi * sinv + b2[2 * l16 + 1];

    float mx = fmaxf(v0, v1);
    #pragma unroll
    for (int o = 8; o > 0; o >>= 1)
        mx = fmaxf(mx, __shfl_xor_sync(0xffffffffu, mx, o));
    float se = fexp(v0 - mx) + fexp(v1 - mx);
    #pragma unroll
    for (int o = 8; o > 0; o >>= 1)
        se += __shfl_xor_sync(0xffffffffu, se, o);
    float lse = mx + __logf(se);
    *(float2*)(out + d * 32 + 2 * l16) = make_float2(v0 - lse, v1 - lse);
}

// ---------------- launch ------------------------------------------------------
extern "C" void kernel_launch(void* const* d_in, const int* in_sizes, int n_in,
                              void* d_out, int out_size)
{
    const float* x   = (const float*)d_in[0];
    const void*  ei  = d_in[1];
    const float* W1  = (const float*)d_in[2];
    const float* as1 = (const float*)d_in[3];
    const float* ad1 = (const float*)d_in[4];
    const float* b1  = (const float*)d_in[5];
    const float* W2  = (const float*)d_in[6];
    const float* as2 = (const float*)d_in[7];
    const float* ad2 = (const float*)d_in[8];
    const float* b2  = (const float*)d_in[9];
    float* out = (float*)d_out;

    int E  = in_sizes[1] / 2;
    int nb = (N_NODES + 1023) / 1024;

    static cudaStream_t s2 = nullptr;
    static cudaEvent_t evF = nullptr, evJ = nullptr;
    if (!s2) {
        cudaStreamCreateWithFlags(&s2, cudaStreamNonBlocking);
        cudaEventCreateWithFlags(&evF, cudaEventDisableTiming);
        cudaEventCreateWithFlags(&evJ, cudaEventDisableTiming);
    }

    cudaEventRecord(evF, 0);
    cudaStreamWaitEvent(s2, evF, 0);

    k_detect<<<1, 1, 0, s2>>>(ei);                              // 1
    k_zero  <<<(N_NODES + 255) / 256, 256, 0, s2>>>();          // 2
    k_conv  <<<(E + 255) / 256, 256, 0, s2>>>(ei, E);           // 3

    k1_gemm1<<<(N_NODES + 63) / 64, 256>>>(x, W1, as1, ad1);    // 4 (profiled)

    kscan1  <<<nb, 1024, 0, s2>>>(N_NODES);                     // 5
    kscan2  <<<1, 128, 0, s2>>>(nb);                            // 6
    kscan3  <<<(N_NODES + 256) / 256, 256, 0, s2>>>(E);         // 7
    k_scat  <<<(E + 255) / 256, 256, 0, s2>>>(ei, E);           // 8
    cudaEventRecord(evJ, s2);

    cudaStreamWaitEvent(0, evJ, 0);

    kA1F    <<<N_NODES / 32, 256>>>(b1, W2, as2, ad2);          // 9
    kA2     <<<N_NODES / 16, 256>>>(b2, out);                   // 10
}